// round 7
// baseline (speedup 1.0000x reference)
#include <cuda_runtime.h>
#include <cuda_bf16.h>
#include <cstdint>
#include <cstddef>

#define BSZ 4
#define SSZ 2048
#define DSZ 4096
#define OSZ 4096
#define ESZ 8
#define RSZ 8
#define MSZ (BSZ*SSZ)            // 8192
#define KLORA (ESZ*RSZ)          // 64
#define KTOT (DSZ+KLORA)         // 4160
#define SCALING 2.0f             // lora_alpha / r = 16/8

// ---------------- scratch (device globals; allocation is forbidden) ----------
__device__ __align__(128) __nv_bfloat16 g_Ahi[(size_t)MSZ*KTOT];
__device__ __align__(128) __nv_bfloat16 g_Alo[(size_t)MSZ*KTOT];
__device__ __align__(128) __nv_bfloat16 g_Bhi[(size_t)OSZ*KTOT];
__device__ __align__(128) __nv_bfloat16 g_Blo[(size_t)OSZ*KTOT];
__device__ float g_weights[BSZ*ESZ];

// ---------------- PTX helpers (all compute_80-era; no tcgen05) --------------
__device__ __forceinline__ uint32_t s2u(const void* p) {
    uint32_t a;
    asm("{ .reg .u64 t; cvta.to.shared.u64 t, %1; cvt.u32.u64 %0, t; }" : "=r"(a) : "l"(p));
    return a;
}
__device__ __forceinline__ void cp16(uint32_t dst, const void* src) {
    asm volatile("cp.async.cg.shared.global [%0], [%1], 16;" :: "r"(dst), "l"(src) : "memory");
}
__device__ __forceinline__ void cp_commit() { asm volatile("cp.async.commit_group;" ::: "memory"); }
template <int N> __device__ __forceinline__ void cp_wait() {
    asm volatile("cp.async.wait_group %0;" :: "n"(N) : "memory");
}
__device__ __forceinline__ void ldsm4(uint32_t* r, uint32_t addr) {
    asm volatile("ldmatrix.sync.aligned.m8n8.x4.shared.b16 {%0,%1,%2,%3}, [%4];"
                 : "=r"(r[0]), "=r"(r[1]), "=r"(r[2]), "=r"(r[3]) : "r"(addr));
}
__device__ __forceinline__ void mma16816(float* c, const uint32_t* a, uint32_t b0, uint32_t b1) {
    asm volatile("mma.sync.aligned.m16n8k16.row.col.f32.bf16.bf16.f32 "
                 "{%0,%1,%2,%3}, {%4,%5,%6,%7}, {%8,%9}, {%0,%1,%2,%3};"
                 : "+f"(c[0]), "+f"(c[1]), "+f"(c[2]), "+f"(c[3])
                 : "r"(a[0]), "r"(a[1]), "r"(a[2]), "r"(a[3]), "r"(b0), "r"(b1));
}

// ---------------- kernel 1: mean-pool + router + softmax --------------------
__global__ __launch_bounds__(256) void k_router(const float* __restrict__ x,
                                                const float* __restrict__ rW,
                                                const float* __restrict__ rb) {
    __shared__ float xm[DSZ];
    __shared__ float lg[ESZ];
    int b = blockIdx.x, tid = threadIdx.x;
    const float inv = 1.0f / SSZ;
    for (int d0 = tid * 4; d0 < DSZ; d0 += 1024) {
        float s0 = 0.f, s1 = 0.f, s2 = 0.f, s3 = 0.f;
        const float* xb = x + (size_t)b*SSZ*DSZ + d0;
        for (int s = 0; s < SSZ; s++) {
            float4 v = *(const float4*)(xb + (size_t)s*DSZ);
            s0 += v.x; s1 += v.y; s2 += v.z; s3 += v.w;
        }
        xm[d0+0] = s0*inv; xm[d0+1] = s1*inv; xm[d0+2] = s2*inv; xm[d0+3] = s3*inv;
    }
    if (tid < ESZ) lg[tid] = 0.f;
    __syncthreads();
    for (int e = 0; e < ESZ; e++) {
        float p = 0.f;
        for (int d = tid; d < DSZ; d += 256) p += xm[d] * rW[(size_t)e*DSZ + d];
        for (int o = 16; o; o >>= 1) p += __shfl_xor_sync(0xffffffffu, p, o);
        if ((tid & 31) == 0) atomicAdd(&lg[e], p);
    }
    __syncthreads();
    if (tid == 0) {
        float l[ESZ], mx = -1e30f;
        for (int e = 0; e < ESZ; e++) { l[e] = lg[e] + rb[e]; mx = fmaxf(mx, l[e]); }
        float sum = 0.f;
        for (int e = 0; e < ESZ; e++) { l[e] = expf(l[e] - mx); sum += l[e]; }
        for (int e = 0; e < ESZ; e++) g_weights[b*ESZ + e] = l[e] / sum;
    }
}

// ---------------- kernel 2: build + split B' = [W_base | SCALING*B_cat] -----
__global__ __launch_bounds__(256) void k_splitB(const float* __restrict__ W,
                                                const float* __restrict__ lB) {
    int o = blockIdx.x;
    for (int k = threadIdx.x; k < KTOT; k += 256) {
        float v;
        if (k < DSZ) v = W[(size_t)o*DSZ + k];
        else {
            int e = (k - DSZ) >> 3, r = (k - DSZ) & 7;
            v = SCALING * lB[((size_t)e*OSZ + o)*RSZ + r];
        }
        __nv_bfloat16 hi = __float2bfloat16(v);
        __nv_bfloat16 lo = __float2bfloat16(v - __bfloat162float(hi));
        size_t off = (size_t)o*KTOT + k;
        g_Bhi[off] = hi; g_Blo[off] = lo;
    }
}

// ---------------- kernel 3: split x into A' cols [0,4096) -------------------
__global__ __launch_bounds__(256) void k_splitX(const float* __restrict__ x) {
    int m = blockIdx.x;
    for (int k = threadIdx.x; k < DSZ; k += 256) {
        float v = x[(size_t)m*DSZ + k];
        __nv_bfloat16 hi = __float2bfloat16(v);
        __nv_bfloat16 lo = __float2bfloat16(v - __bfloat162float(hi));
        size_t off = (size_t)m*KTOT + k;
        g_Ahi[off] = hi; g_Alo[off] = lo;
    }
}

// ---------------- kernel 4: h = x@A_cat^T, router-weight, split -------------
__global__ __launch_bounds__(256) void k_h(const float* __restrict__ x,
                                           const float* __restrict__ lA) {
    __shared__ float xs[64][65];
    __shared__ float as[64][65];
    int tid = threadIdx.x;
    int m0 = blockIdx.x * 64;
    int ty = tid >> 4, tx = tid & 15;
    float acc[4][4] = {};
    for (int kt = 0; kt < DSZ; kt += 64) {
        __syncthreads();
#pragma unroll
        for (int i = 0; i < 16; i++) {
            int q = tid + i*256;
            int r = q >> 6, c = q & 63;
            xs[r][c] = x[(size_t)(m0 + r)*DSZ + kt + c];
            as[r][c] = lA[(size_t)r*DSZ + kt + c];    // lora_A viewed [64,4096]
        }
        __syncthreads();
#pragma unroll 8
        for (int kk = 0; kk < 64; kk++) {
            float xv[4], av[4];
#pragma unroll
            for (int i = 0; i < 4; i++) xv[i] = xs[ty*4 + i][kk];
#pragma unroll
            for (int j = 0; j < 4; j++) av[j] = as[tx*4 + j][kk];
#pragma unroll
            for (int i = 0; i < 4; i++)
#pragma unroll
                for (int j = 0; j < 4; j++) acc[i][j] += xv[i]*av[j];
        }
    }
#pragma unroll
    for (int i = 0; i < 4; i++) {
        int m = m0 + ty*4 + i;
        int b = m >> 11;
#pragma unroll
        for (int j = 0; j < 4; j++) {
            int c = tx*4 + j;
            float v = acc[i][j] * g_weights[b*ESZ + (c >> 3)];
            __nv_bfloat16 hi = __float2bfloat16(v);
            __nv_bfloat16 lo = __float2bfloat16(v - __bfloat162float(hi));
            size_t off = (size_t)m*KTOT + DSZ + c;
            g_Ahi[off] = hi; g_Alo[off] = lo;
        }
    }
}

// ---------------- kernel 5: main GEMM, mma.sync bf16 3-pass -----------------
// CTA tile 128Mx128N, KC=32, 2-stage cp.async pipeline.
// smem stage = 4 tiles (Ahi,Alo,Bhi,Blo), each 128 rows x 32 bf16 (64B rows,
// 16B chunks XOR-swizzled: pc = c ^ (r&3)).
#define KC2   32
#define NKT2  (KTOT/KC2)         // 130
#define TILEB (128*32*2)         // 8192
#define STAGEB (4*TILEB)         // 32768
#define GEMM_SMEM (2*STAGEB)     // 65536

__global__ __launch_bounds__(256, 1) void k_gemm(const float* __restrict__ bias,
                                                 float* __restrict__ out) {
    extern __shared__ char smem[];
    const uint32_t sb = s2u(smem);
    const int tid = threadIdx.x;
    const int m0 = blockIdx.y * 128;
    const int n0 = blockIdx.x * 128;
    const int w = tid >> 5, l = tid & 31;
    const int mw = (w & 1) * 64;       // warp M offset (2 warps in M)
    const int nw = (w >> 1) * 32;      // warp N offset (4 warps in N)

    // ldmatrix lane mappings
    const int rA = l & 15, halfA = l >> 4;                 // A: rows m0..15, k-half
    const int rB = ((l >> 4) & 1) * 8 + (l & 7);           // B: n rows
    const int halfB = (l >> 3) & 1;                        // B: k-half

    const __nv_bfloat16* srcs[4] = { g_Ahi, g_Alo, g_Bhi, g_Blo };
    const int row0s[4] = { m0, m0, n0, n0 };

    float acc[4][4][4];
#pragma unroll
    for (int a = 0; a < 4; a++)
#pragma unroll
        for (int b = 0; b < 4; b++)
#pragma unroll
            for (int c = 0; c < 4; c++) acc[a][b][c] = 0.f;

    // prologue: stage 0 <- chunk 0
    {
        uint32_t base = sb;
#pragma unroll
        for (int t = 0; t < 4; t++) {
            const __nv_bfloat16* src = srcs[t];
#pragma unroll
            for (int i = 0; i < 2; i++) {
                int u = tid + i*256;
                int r = u >> 2, c = u & 3, pc = c ^ (r & 3);
                cp16(base + t*TILEB + r*64 + pc*16,
                     src + (size_t)(row0s[t] + r)*KTOT + c*8);
            }
        }
        cp_commit();
    }

    for (int kt = 0; kt < NKT2; kt++) {
        int s = kt & 1;
        if (kt + 1 < NKT2) {
            uint32_t base = sb + (s ^ 1) * STAGEB;
            int k0 = (kt + 1) * KC2;
#pragma unroll
            for (int t = 0; t < 4; t++) {
                const __nv_bfloat16* src = srcs[t];
#pragma unroll
                for (int i = 0; i < 2; i++) {
                    int u = tid + i*256;
                    int r = u >> 2, c = u & 3, pc = c ^ (r & 3);
                    cp16(base + t*TILEB + r*64 + pc*16,
                         src + (size_t)(row0s[t] + r)*KTOT + k0 + c*8);
                }
            }
            cp_commit();
            cp_wait<1>();         // chunk kt's group complete
        } else {
            cp_wait<0>();
        }
        __syncthreads();

        uint32_t At_hi = sb + s*STAGEB;
        uint32_t At_lo = At_hi + TILEB;
        uint32_t Bt_hi = At_hi + 2*TILEB;
        uint32_t Bt_lo = At_hi + 3*TILEB;

#pragma unroll
        for (int ks = 0; ks < 2; ks++) {
            uint32_t ah[4][4], al[4][4], bh[2][4], bl[2][4];
#pragma unroll
            for (int mt = 0; mt < 4; mt++) {
                int r = mw + mt*16 + rA;
                uint32_t off = (uint32_t)(r*64 + (((2*ks + halfA) ^ (r & 3)) * 16));
                ldsm4(ah[mt], At_hi + off);
                ldsm4(al[mt], At_lo + off);
            }
#pragma unroll
            for (int np = 0; np < 2; np++) {
                int r = nw + np*16 + rB;
                uint32_t off = (uint32_t)(r*64 + (((2*ks + halfB) ^ (r & 3)) * 16));
                ldsm4(bh[np], Bt_hi + off);
                ldsm4(bl[np], Bt_lo + off);
            }
#pragma unroll
            for (int mt = 0; mt < 4; mt++)
#pragma unroll
                for (int nt = 0; nt < 4; nt++) {
                    int np = nt >> 1, h = (nt & 1) * 2;
                    mma16816(acc[mt][nt], ah[mt], bh[np][h], bh[np][h+1]);
                    mma16816(acc[mt][nt], ah[mt], bl[np][h], bl[np][h+1]);
                    mma16816(acc[mt][nt], al[mt], bh[np][h], bh[np][h+1]);
                }
        }
        __syncthreads();
    }

    // epilogue: add bias, store fp32
#pragma unroll
    for (int mt = 0; mt < 4; mt++) {
        int row = m0 + mw + mt*16 + (l >> 2);
#pragma unroll
        for (int nt = 0; nt < 4; nt++) {
            int col = n0 + nw + nt*8 + (l & 3)*2;
            float b0 = bias[col], b1 = bias[col+1];
            float* p0 = out + (size_t)row*OSZ + col;
            float* p1 = out + (size_t)(row + 8)*OSZ + col;
            float2 v0 = { acc[mt][nt][0] + b0, acc[mt][nt][1] + b1 };
            float2 v1 = { acc[mt][nt][2] + b0, acc[mt][nt][3] + b1 };
            *(float2*)p0 = v0;
            *(float2*)p1 = v1;
        }
    }
}

// ---------------- launch ----------------
extern "C" void kernel_launch(void* const* d_in, const int* in_sizes, int n_in,
                              void* d_out, int out_size) {
    const float* x  = (const float*)d_in[0];
    const float* Wb = (const float*)d_in[1];
    const float* bb = (const float*)d_in[2];
    const float* lA = (const float*)d_in[3];
    const float* lB = (const float*)d_in[4];
    const float* rW = (const float*)d_in[5];
    const float* rb = (const float*)d_in[6];
    float* out = (float*)d_out;

    cudaFuncSetAttribute((const void*)k_gemm,
                         cudaFuncAttributeMaxDynamicSharedMemorySize, GEMM_SMEM);

    k_router<<<BSZ, 256>>>(x, rW, rb);
    k_splitB<<<OSZ, 256>>>(Wb, lB);
    k_splitX<<<MSZ, 256>>>(x);
    k_h<<<MSZ/64, 256>>>(x, lA);
    k_gemm<<<dim3(OSZ/128, MSZ/128), 256, GEMM_SMEM>>>(bb, out);
}

// round 8
// speedup vs baseline: 3.6092x; 3.6092x over previous
#include <cuda_runtime.h>
#include <cuda_fp16.h>
#include <cstdint>
#include <cstddef>

#define BSZ 4
#define SSZ 2048
#define DSZ 4096
#define OSZ 4096
#define ESZ 8
#define RSZ 8
#define MSZ (BSZ*SSZ)            // 8192
#define KLORA (ESZ*RSZ)          // 64
#define KTOT (DSZ+KLORA)         // 4160
#define SCALING 2.0f             // lora_alpha / r = 16/8

// ---------------- scratch (device globals; allocation is forbidden) ----------
__device__ __align__(128) __half g_Ah[(size_t)MSZ*KTOT];   // [x | hw] fp16
__device__ __align__(128) __half g_Bh[(size_t)OSZ*KTOT];   // [W | 2*B_cat] fp16
__device__ float g_xmean[BSZ*DSZ];
__device__ float g_weights[BSZ*ESZ];

// ---------------- PTX helpers (compute_80-era; sm_103 virtual-arch safe) ----
__device__ __forceinline__ uint32_t s2u(const void* p) {
    uint32_t a;
    asm("{ .reg .u64 t; cvta.to.shared.u64 t, %1; cvt.u32.u64 %0, t; }" : "=r"(a) : "l"(p));
    return a;
}
__device__ __forceinline__ void cp16(uint32_t dst, const void* src) {
    asm volatile("cp.async.cg.shared.global [%0], [%1], 16;" :: "r"(dst), "l"(src) : "memory");
}
__device__ __forceinline__ void cp_commit() { asm volatile("cp.async.commit_group;" ::: "memory"); }
template <int N> __device__ __forceinline__ void cp_wait() {
    asm volatile("cp.async.wait_group %0;" :: "n"(N) : "memory");
}
__device__ __forceinline__ void ldsm4(uint32_t* r, uint32_t addr) {
    asm volatile("ldmatrix.sync.aligned.m8n8.x4.shared.b16 {%0,%1,%2,%3}, [%4];"
                 : "=r"(r[0]), "=r"(r[1]), "=r"(r[2]), "=r"(r[3]) : "r"(addr));
}
__device__ __forceinline__ void mma16816(float* c, const uint32_t* a, uint32_t b0, uint32_t b1) {
    asm volatile("mma.sync.aligned.m16n8k16.row.col.f32.f16.f16.f32 "
                 "{%0,%1,%2,%3}, {%4,%5,%6,%7}, {%8,%9}, {%0,%1,%2,%3};"
                 : "+f"(c[0]), "+f"(c[1]), "+f"(c[2]), "+f"(c[3])
                 : "r"(a[0]), "r"(a[1]), "r"(a[2]), "r"(a[3]), "r"(b0), "r"(b1));
}

// ---------------- kernel 0: zero the pooled-mean buffer ---------------------
__global__ void k_zero() {
    int i = blockIdx.x * blockDim.x + threadIdx.x;
    if (i < BSZ*DSZ) g_xmean[i] = 0.f;
}

// ---------------- kernel 1a: parallel mean pool (grid B x 16) ---------------
__global__ __launch_bounds__(256) void k_pool(const float* __restrict__ x) {
    int b = blockIdx.x;
    int s0 = blockIdx.y * (SSZ/16);
    const float inv = 1.0f / SSZ;
    // each thread owns 16 d-indices: tid*4 + {0..3} at 4 strided groups of 1024
    float acc[4][4] = {};
    const float* xb = x + (size_t)b*SSZ*DSZ;
    for (int s = s0; s < s0 + SSZ/16; s++) {
        const float* row = xb + (size_t)s*DSZ;
#pragma unroll
        for (int g = 0; g < 4; g++) {
            float4 v = *(const float4*)(row + g*1024 + threadIdx.x*4);
            acc[g][0] += v.x; acc[g][1] += v.y; acc[g][2] += v.z; acc[g][3] += v.w;
        }
    }
#pragma unroll
    for (int g = 0; g < 4; g++)
#pragma unroll
        for (int j = 0; j < 4; j++)
            atomicAdd(&g_xmean[b*DSZ + g*1024 + threadIdx.x*4 + j], acc[g][j] * inv);
}

// ---------------- kernel 1b: router logits + softmax (1 block) --------------
__global__ __launch_bounds__(256) void k_logits(const float* __restrict__ rW,
                                                const float* __restrict__ rb) {
    __shared__ float lg[BSZ][ESZ];
    int tid = threadIdx.x;
    if (tid < BSZ*ESZ) ((float*)lg)[tid] = 0.f;
    __syncthreads();
    for (int be = 0; be < BSZ*ESZ; be++) {
        int b = be >> 3, e = be & 7;
        float p = 0.f;
        for (int d = tid; d < DSZ; d += 256) p += g_xmean[b*DSZ + d] * rW[(size_t)e*DSZ + d];
        for (int o = 16; o; o >>= 1) p += __shfl_xor_sync(0xffffffffu, p, o);
        if ((tid & 31) == 0) atomicAdd(&lg[b][e], p);
    }
    __syncthreads();
    if (tid < BSZ) {
        int b = tid;
        float l[ESZ], mx = -1e30f;
        for (int e = 0; e < ESZ; e++) { l[e] = lg[b][e] + rb[e]; mx = fmaxf(mx, l[e]); }
        float sum = 0.f;
        for (int e = 0; e < ESZ; e++) { l[e] = expf(l[e] - mx); sum += l[e]; }
        for (int e = 0; e < ESZ; e++) g_weights[b*ESZ + e] = l[e] / sum;
    }
}

// ---------------- kernel 2: B' = [W_base | SCALING*B_cat] -> fp16 -----------
__global__ __launch_bounds__(256) void k_cvtB(const float* __restrict__ W,
                                              const float* __restrict__ lB) {
    int o = blockIdx.x;
    // base part: 4096 cols, float4
    for (int c4 = threadIdx.x; c4 < DSZ/4; c4 += 256) {
        float4 v = *(const float4*)(W + (size_t)o*DSZ + c4*4);
        size_t off = (size_t)o*KTOT + c4*4;
        g_Bh[off+0] = __float2half(v.x); g_Bh[off+1] = __float2half(v.y);
        g_Bh[off+2] = __float2half(v.z); g_Bh[off+3] = __float2half(v.w);
    }
    // lora part: 64 cols
    if (threadIdx.x < KLORA) {
        int k = threadIdx.x;
        int e = k >> 3, r = k & 7;
        float v = SCALING * lB[((size_t)e*OSZ + o)*RSZ + r];
        g_Bh[(size_t)o*KTOT + DSZ + k] = __float2half(v);
    }
}

// ---------------- kernel 3: x -> fp16 into A' cols [0,4096) -----------------
__global__ __launch_bounds__(256) void k_cvtX(const float* __restrict__ x) {
    int m = blockIdx.x;
    for (int c4 = threadIdx.x; c4 < DSZ/4; c4 += 256) {
        float4 v = *(const float4*)(x + (size_t)m*DSZ + c4*4);
        size_t off = (size_t)m*KTOT + c4*4;
        g_Ah[off+0] = __float2half(v.x); g_Ah[off+1] = __float2half(v.y);
        g_Ah[off+2] = __float2half(v.z); g_Ah[off+3] = __float2half(v.w);
    }
}

// ---------------- kernel 4: h = x@A_cat^T, router-weight -> fp16 ------------
// 256 CTAs x 32 rows, fp32 SIMT, float4 global loads.
__global__ __launch_bounds__(256) void k_h(const float* __restrict__ x,
                                           const float* __restrict__ lA) {
    __shared__ float xs[32][65];
    __shared__ float as[64][65];
    int tid = threadIdx.x;
    int m0 = blockIdx.x * 32;
    int ty = tid >> 4, tx = tid & 15;     // 16x16 threads; 2 rows x 4 cols each
    float acc[2][4] = {};
    for (int kt = 0; kt < DSZ; kt += 64) {
        __syncthreads();
        // xs: 32x64 floats = 512 float4, 2 per thread
#pragma unroll
        for (int i = 0; i < 2; i++) {
            int q = tid + i*256;
            int r = q >> 4, c4 = q & 15;
            float4 v = *(const float4*)(x + (size_t)(m0 + r)*DSZ + kt + c4*4);
            xs[r][c4*4+0] = v.x; xs[r][c4*4+1] = v.y; xs[r][c4*4+2] = v.z; xs[r][c4*4+3] = v.w;
        }
        // as: 64x64 floats = 1024 float4, 4 per thread
#pragma unroll
        for (int i = 0; i < 4; i++) {
            int q = tid + i*256;
            int r = q >> 4, c4 = q & 15;
            float4 v = *(const float4*)(lA + (size_t)r*DSZ + kt + c4*4);
            as[r][c4*4+0] = v.x; as[r][c4*4+1] = v.y; as[r][c4*4+2] = v.z; as[r][c4*4+3] = v.w;
        }
        __syncthreads();
#pragma unroll 8
        for (int kk = 0; kk < 64; kk++) {
            float xv[2], av[4];
            xv[0] = xs[ty*2 + 0][kk];
            xv[1] = xs[ty*2 + 1][kk];
#pragma unroll
            for (int j = 0; j < 4; j++) av[j] = as[tx*4 + j][kk];
#pragma unroll
            for (int i = 0; i < 2; i++)
#pragma unroll
                for (int j = 0; j < 4; j++) acc[i][j] += xv[i]*av[j];
        }
    }
#pragma unroll
    for (int i = 0; i < 2; i++) {
        int m = m0 + ty*2 + i;
        int b = m >> 11;
#pragma unroll
        for (int j = 0; j < 4; j++) {
            int c = tx*4 + j;
            float v = acc[i][j] * g_weights[b*ESZ + (c >> 3)];
            g_Ah[(size_t)m*KTOT + DSZ + c] = __float2half(v);
        }
    }
}

// ---------------- kernel 5: main GEMM, fp16 single pass ---------------------
// CTA tile 128Mx128N, KC=64, 2-stage cp.async pipeline.
// Tile rows are 128B (64 fp16), 8x16B chunks, XOR swizzle pc = c ^ (r&7).
#define KC2   64
#define NKT2  (KTOT/KC2)         // 65
#define TILEB (128*64*2)         // 16384
#define STAGEB (2*TILEB)         // 32768 (A + B)
#define GEMM_SMEM (2*STAGEB)     // 65536

__global__ __launch_bounds__(256, 2) void k_gemm(const float* __restrict__ bias,
                                                 float* __restrict__ out) {
    extern __shared__ char smem[];
    const uint32_t sb = s2u(smem);
    const int tid = threadIdx.x;
    const int m0 = blockIdx.y * 128;
    const int n0 = blockIdx.x * 128;
    const int w = tid >> 5, l = tid & 31;
    const int mw = (w & 1) * 64;       // 2 warps in M
    const int nw = (w >> 1) * 32;      // 4 warps in N

    // ldmatrix lane mappings (verified in R6)
    const int rA = l & 15, halfA = l >> 4;
    const int rB = ((l >> 4) & 1) * 8 + (l & 7);
    const int halfB = (l >> 3) & 1;

    const __half* srcA = g_Ah + (size_t)m0*KTOT;
    const __half* srcB = g_Bh + (size_t)n0*KTOT;

    float acc[4][4][4];
#pragma unroll
    for (int a = 0; a < 4; a++)
#pragma unroll
        for (int b = 0; b < 4; b++)
#pragma unroll
            for (int c = 0; c < 4; c++) acc[a][b][c] = 0.f;

    // prologue: stage 0 <- chunk 0  (per tile: 1024 cp16 -> 4 per thread)
    {
#pragma unroll
        for (int i = 0; i < 4; i++) {
            int u = tid + i*256;
            int r = u >> 3, c = u & 7, pc = c ^ (r & 7);
            cp16(sb + r*128 + pc*16, srcA + (size_t)r*KTOT + c*8);
            cp16(sb + TILEB + r*128 + pc*16, srcB + (size_t)r*KTOT + c*8);
        }
        cp_commit();
    }

    for (int kt = 0; kt < NKT2; kt++) {
        int s = kt & 1;
        if (kt + 1 < NKT2) {
            uint32_t base = sb + (s ^ 1) * STAGEB;
            int k0 = (kt + 1) * KC2;
#pragma unroll
            for (int i = 0; i < 4; i++) {
                int u = tid + i*256;
                int r = u >> 3, c = u & 7, pc = c ^ (r & 7);
                cp16(base + r*128 + pc*16, srcA + (size_t)r*KTOT + k0 + c*8);
                cp16(base + TILEB + r*128 + pc*16, srcB + (size_t)r*KTOT + k0 + c*8);
            }
            cp_commit();
            cp_wait<1>();   // chunk kt's group complete
        } else {
            cp_wait<0>();
        }
        __syncthreads();

        uint32_t At = sb + s*STAGEB;
        uint32_t Bt = At + TILEB;

#pragma unroll
        for (int ks = 0; ks < 4; ks++) {
            uint32_t a[4][4], b[2][4];
#pragma unroll
            for (int mt = 0; mt < 4; mt++) {
                int r = mw + mt*16 + rA;
                uint32_t off = (uint32_t)(r*128 + (((2*ks + halfA) ^ (r & 7)) * 16));
                ldsm4(a[mt], At + off);
            }
#pragma unroll
            for (int np = 0; np < 2; np++) {
                int r = nw + np*16 + rB;
                uint32_t off = (uint32_t)(r*128 + (((2*ks + halfB) ^ (r & 7)) * 16));
                ldsm4(b[np], Bt + off);
            }
#pragma unroll
            for (int mt = 0; mt < 4; mt++)
#pragma unroll
                for (int nt = 0; nt < 4; nt++) {
                    int np = nt >> 1, h = (nt & 1) * 2;
                    mma16816(acc[mt][nt], a[mt], b[np][h], b[np][h+1]);
                }
        }
        __syncthreads();
    }

    // epilogue: add bias, store fp32
#pragma unroll
    for (int mt = 0; mt < 4; mt++) {
        int row = m0 + mw + mt*16 + (l >> 2);
#pragma unroll
        for (int nt = 0; nt < 4; nt++) {
            int col = n0 + nw + nt*8 + (l & 3)*2;
            float b0 = bias[col], b1 = bias[col+1];
            float* p0 = out + (size_t)row*OSZ + col;
            float* p1 = out + (size_t)(row + 8)*OSZ + col;
            float2 v0 = { acc[mt][nt][0] + b0, acc[mt][nt][1] + b1 };
            float2 v1 = { acc[mt][nt][2] + b0, acc[mt][nt][3] + b1 };
            *(float2*)p0 = v0;
            *(float2*)p1 = v1;
        }
    }
}

// ---------------- launch ----------------
extern "C" void kernel_launch(void* const* d_in, const int* in_sizes, int n_in,
                              void* d_out, int out_size) {
    const float* x  = (const float*)d_in[0];
    const float* Wb = (const float*)d_in[1];
    const float* bb = (const float*)d_in[2];
    const float* lA = (const float*)d_in[3];
    const float* lB = (const float*)d_in[4];
    const float* rW = (const float*)d_in[5];
    const float* rb = (const float*)d_in[6];
    float* out = (float*)d_out;

    cudaFuncSetAttribute((const void*)k_gemm,
                         cudaFuncAttributeMaxDynamicSharedMemorySize, GEMM_SMEM);

    k_zero<<<(BSZ*DSZ + 255)/256, 256>>>();
    k_pool<<<dim3(BSZ, 16), 256>>>(x);
    k_logits<<<1, 256>>>(rW, rb);
    k_cvtB<<<OSZ, 256>>>(Wb, lB);
    k_cvtX<<<MSZ, 256>>>(x);
    k_h<<<MSZ/32, 256>>>(x, lA);
    k_gemm<<<dim3(OSZ/128, MSZ/128), 256, GEMM_SMEM>>>(bb, out);
}